// round 15
// baseline (speedup 1.0000x reference)
#include <cuda_runtime.h>
#include <cuda_bf16.h>
#include <cstdint>

// Problem shapes (fixed by the dataset's setup_inputs)
constexpr int B = 16;
constexpr int S = 512;
constexpr int D = 768;     // span_dim
constexpr int E = 128;     // distance embedding dim
constexpr int T = 64;
constexpr int O = 64;
constexpr int P = T * O;            // 4096 pairs per batch
constexpr int OUT_D = 2 * D + E;    // 1664 floats per output row
constexpr int D4 = D / 4;           // 192 float4
constexpr int E4 = E / 4;           // 32 float4
constexpr int OUT_D4 = OUT_D / 4;   // 416 float4
constexpr int NBINS = 14;
constexpr int TILE_BYTES = 2 * OUT_D4 * 16;   // 13312 B (two rows)

// bucket = (# bins <= width) - 1; bins[0]=0 and width>=0,
// so bucket = sum_{i=1..13} (width >= bins[i]).
__constant__ int c_bins[NBINS] = {0, 1, 2, 3, 4, 5, 7, 8, 15, 16, 31, 32, 63, 64};

__device__ __forceinline__ int bucketize(int w) {
    int bucket = 0;
#pragma unroll
    for (int i = 1; i < NBINS; ++i)
        bucket += (w >= c_bins[i]) ? 1 : 0;
    return bucket;
}

__device__ __forceinline__ uint32_t smem_u32(const void* p) {
    uint32_t a;
    asm("{ .reg .u64 t; cvta.to.shared.u64 t, %1; cvt.u32.u64 %0, t; }"
        : "=r"(a) : "l"(p));
    return a;
}

// Champion geometry (2 rows/block: same target, adjacent opinions;
// 32768 blocks x 192 threads) with the STORE PATH replaced by TMA:
// both output rows are assembled in smem (conflict-free STS.128), then ONE
// cp.async.bulk (13312 B) writes them to global. This removes ~104 STG.128
// wavefronts per block from the L1tex pipe (L1 was at 74%) and emits full
// 128B-line DRAM writes from the TMA engine with no write-allocate.
__global__ __launch_bounds__(192, 10)
void pair_rep_kernel(const float4* __restrict__ spans,      // [B,S,D/4]
                     const float4* __restrict__ dist_emb,   // [14,E/4]
                     const int2*   __restrict__ span_idx,   // [S]
                     const int*    __restrict__ tgt,        // [B,T]
                     const int*    __restrict__ opi,        // [B,O]
                     float4*       __restrict__ out)        // [B*P, OUT_D/4]
{
    __shared__ __align__(128) float4 s_buf[2 * OUT_D4];    // 13312 B

    const int blk = blockIdx.x;            // 0 .. B*T*(O/2)-1
    const int b   = blk >> 11;             // / 2048
    const int r   = blk & 2047;
    const int t   = r >> 5;                // / 32
    const int g   = r & 31;                // opinion pair group
    const int o0  = 2 * g;

    const int ti  = __ldg(&tgt[b * T + t]);
    const int oiA = __ldg(&opi[b * O + o0]);
    const int oiB = __ldg(&opi[b * O + o0 + 1]);

    const int tid = threadIdx.x;           // 0..191 == D4
    const float4* spb = spans + (size_t)b * S * D4;

    // Hoist all independent loads (vt reused for both rows)
    const float4 vt  = __ldg(&spb[(size_t)ti  * D4 + tid]);
    const float4 voA = __ldg(&spb[(size_t)oiA * D4 + tid]);
    const float4 voB = __ldg(&spb[(size_t)oiB * D4 + tid]);

    if (tid < E4) {
        const int2 ab  = __ldg(&span_idx[ti]);
        const int2 cdA = __ldg(&span_idx[oiA]);
        const int2 cdB = __ldg(&span_idx[oiB]);
        const int bkA = bucketize(min(abs(ab.y - cdA.x), abs(ab.x - cdA.y)));
        const int bkB = bucketize(min(abs(ab.y - cdB.x), abs(ab.x - cdB.y)));
        s_buf[2 * D4 + tid]          = __ldg(&dist_emb[(size_t)bkA * E4 + tid]);
        s_buf[OUT_D4 + 2 * D4 + tid] = __ldg(&dist_emb[(size_t)bkB * E4 + tid]);
    }

    // Assemble both rows in smem (conflict-free: contiguous 16B per lane)
    s_buf[tid]               = vt;
    s_buf[D4 + tid]          = voA;
    s_buf[OUT_D4 + tid]      = vt;
    s_buf[OUT_D4 + D4 + tid] = voB;

    __syncthreads();
    // Make generic-proxy smem writes visible to the async (TMA) proxy
    asm volatile("fence.proxy.async.shared::cta;" ::: "memory");

    if (tid == 0) {
        float4* dst = out + ((size_t)b * P + (size_t)t * O + o0) * OUT_D4;
        const uint32_t saddr = smem_u32(s_buf);
        asm volatile(
            "cp.async.bulk.global.shared::cta.bulk_group [%0], [%1], %2;"
            :: "l"(dst), "r"(saddr), "r"((uint32_t)TILE_BYTES) : "memory");
        asm volatile("cp.async.bulk.commit_group;" ::: "memory");
        // Wait until TMA has READ the smem before the CTA can retire
        asm volatile("cp.async.bulk.wait_group.read 0;" ::: "memory");
    }
}

extern "C" void kernel_launch(void* const* d_in, const int* in_sizes, int n_in,
                              void* d_out, int out_size)
{
    // metadata order: spans, dist_emb, span_indices, target_indices, opinion_indices
    const float4* spans    = (const float4*)d_in[0];
    const float4* dist_emb = (const float4*)d_in[1];
    const int2*   span_idx = (const int2*)  d_in[2];
    const int*    tgt      = (const int*)   d_in[3];
    const int*    opi      = (const int*)   d_in[4];
    float4*       out      = (float4*)d_out;

    dim3 grid(B * T * (O / 2));   // 32768 blocks, two rows each
    dim3 block(192);
    pair_rep_kernel<<<grid, block>>>(spans, dist_emb, span_idx, tgt, opi, out);
}

// round 16
// speedup vs baseline: 1.1150x; 1.1150x over previous
#include <cuda_runtime.h>
#include <cuda_bf16.h>
#include <cstdint>

// Problem shapes (fixed by the dataset's setup_inputs)
constexpr int B = 16;
constexpr int S = 512;
constexpr int D = 768;     // span_dim
constexpr int E = 128;     // distance embedding dim
constexpr int T = 64;
constexpr int O = 64;
constexpr int P = T * O;            // 4096 pairs per batch
constexpr int OUT_D = 2 * D + E;    // 1664 floats per output row
constexpr int D4 = D / 4;           // 192 float4
constexpr int E4 = E / 4;           // 32 float4
constexpr int OUT_D4 = OUT_D / 4;   // 416 float4
constexpr int NBINS = 14;

// bucket = (# bins <= width) - 1; bins[0]=0 and width>=0,
// so bucket = sum_{i=1..13} (width >= bins[i]).
__constant__ int c_bins[NBINS] = {0, 1, 2, 3, 4, 5, 7, 8, 15, 16, 31, 32, 63, 64};

__device__ __forceinline__ int bucketize(int w) {
    int bucket = 0;
#pragma unroll
    for (int i = 1; i < NBINS; ++i)
        bucket += (w >= c_bins[i]) ? 1 : 0;
    return bucket;
}

// FINAL CHAMPION (session best: 61.9 us; re-measured 62.2 twice — noise band).
// One block handles 2 output rows: same target, adjacent opinions.
// 32768 blocks x 192 threads. The target-span float4 is loaded once per
// thread and reused for both rows (-24% LTS read traffic vs 1-row/block);
// all loads are hoisted ahead of all stores (MLP up to 5 per thread); all
// stores are streaming (__stcs) coalesced float4.
//
// Verified-bound analysis (rounds 1-15): the kernel saturates the LTS
// crossbar (~12 TB/s total L2 traffic) jointly with the HBM write stream.
// Tested and rejected: deeper tiling (2x2, 1x4, 4x4 — occupancy/ILP loss
// beats traffic gain), smem staging, warp specialization, 256t blocks,
// default-policy stores (+5.4us), TMA bulk stores (+6.6us; LTS cap is
// path-independent), scoreboard reordering (neutral).
__global__ __launch_bounds__(192, 10)
void pair_rep_kernel(const float4* __restrict__ spans,      // [B,S,D/4]
                     const float4* __restrict__ dist_emb,   // [14,E/4]
                     const int2*   __restrict__ span_idx,   // [S]
                     const int*    __restrict__ tgt,        // [B,T]
                     const int*    __restrict__ opi,        // [B,O]
                     float4*       __restrict__ out)        // [B*P, OUT_D/4]
{
    const int blk = blockIdx.x;            // 0 .. B*T*(O/2)-1
    const int b   = blk >> 11;             // / 2048
    const int r   = blk & 2047;
    const int t   = r >> 5;                // / 32
    const int g   = r & 31;                // opinion pair group
    const int o0  = 2 * g;

    const int ti  = __ldg(&tgt[b * T + t]);
    const int oiA = __ldg(&opi[b * O + o0]);
    const int oiB = __ldg(&opi[b * O + o0 + 1]);

    const int2 ab = __ldg(&span_idx[ti]);
    const int2 cdA = __ldg(&span_idx[oiA]);
    const int2 cdB = __ldg(&span_idx[oiB]);
    const int wA = min(abs(ab.y - cdA.x), abs(ab.x - cdA.y));
    const int wB = min(abs(ab.y - cdB.x), abs(ab.x - cdB.y));
    const int bkA = bucketize(wA);
    const int bkB = bucketize(wB);

    const int tid = threadIdx.x;           // 0..191 == D4

    const float4* spb = spans + (size_t)b * S * D4;

    // Hoist all independent loads (vt reused for both rows)
    const float4 vt  = __ldg(&spb[(size_t)ti  * D4 + tid]);
    const float4 voA = __ldg(&spb[(size_t)oiA * D4 + tid]);
    const float4 voB = __ldg(&spb[(size_t)oiB * D4 + tid]);
    float4 vdA, vdB;
    if (tid < E4) {
        vdA = __ldg(&dist_emb[(size_t)bkA * E4 + tid]);
        vdB = __ldg(&dist_emb[(size_t)bkB * E4 + tid]);
    }

    float4* dst = out + ((size_t)b * P + (size_t)t * O + o0) * OUT_D4;

    // Row A
    __stcs(&dst[tid], vt);
    __stcs(&dst[D4 + tid], voA);
    if (tid < E4) __stcs(&dst[2 * D4 + tid], vdA);
    // Row B
    __stcs(&dst[OUT_D4 + tid], vt);
    __stcs(&dst[OUT_D4 + D4 + tid], voB);
    if (tid < E4) __stcs(&dst[OUT_D4 + 2 * D4 + tid], vdB);
}

extern "C" void kernel_launch(void* const* d_in, const int* in_sizes, int n_in,
                              void* d_out, int out_size)
{
    // metadata order: spans, dist_emb, span_indices, target_indices, opinion_indices
    const float4* spans    = (const float4*)d_in[0];
    const float4* dist_emb = (const float4*)d_in[1];
    const int2*   span_idx = (const int2*)  d_in[2];
    const int*    tgt      = (const int*)   d_in[3];
    const int*    opi      = (const int*)   d_in[4];
    float4*       out      = (float4*)d_out;

    dim3 grid(B * T * (O / 2));   // 32768 blocks, two rows each
    dim3 block(192);
    pair_rep_kernel<<<grid, block>>>(spans, dist_emb, span_idx, tgt, opi, out);
}